// round 14
// baseline (speedup 1.0000x reference)
#include <cuda_runtime.h>
#include <cuda_bf16.h>
#include <cuda_fp16.h>
#include <math.h>
#include <cstdint>

#define NB 32
#define NT 1024
#define NC 768
#define ND 64

// ---- helpers ----
__device__ __forceinline__ uint32_t pack_bf2(float lo, float hi) {
    uint32_t r; asm("cvt.rn.bf16x2.f32 %0, %1, %2;" : "=r"(r) : "f"(hi), "f"(lo)); return r;
}
__device__ __forceinline__ float lo_bf(uint32_t h) { return __uint_as_float(h << 16); }
__device__ __forceinline__ float hi_bf(uint32_t h) { return __uint_as_float(h & 0xffff0000u); }

__device__ __forceinline__ void mma16816(float* c, const uint32_t* a, const uint32_t* b) {
    asm volatile(
        "mma.sync.aligned.m16n8k16.row.col.f32.bf16.bf16.f32 "
        "{%0,%1,%2,%3}, {%4,%5,%6,%7}, {%8,%9}, {%0,%1,%2,%3};"
        : "+f"(c[0]), "+f"(c[1]), "+f"(c[2]), "+f"(c[3])
        : "r"(a[0]), "r"(a[1]), "r"(a[2]), "r"(a[3]), "r"(b[0]), "r"(b[1]));
}
__device__ __forceinline__ void mma_f16(float* c, const uint32_t* a, const uint32_t* b) {
    asm volatile(
        "mma.sync.aligned.m16n8k16.row.col.f32.f16.f16.f32 "
        "{%0,%1,%2,%3}, {%4,%5,%6,%7}, {%8,%9}, {%0,%1,%2,%3};"
        : "+f"(c[0]), "+f"(c[1]), "+f"(c[2]), "+f"(c[3])
        : "r"(a[0]), "r"(a[1]), "r"(a[2]), "r"(a[3]), "r"(b[0]), "r"(b[1]));
}
#define LDM4(r, addr) \
    asm volatile("ldmatrix.sync.aligned.m8n8.x4.shared.b16 {%0,%1,%2,%3}, [%4];" \
        : "=r"((r)[0]), "=r"((r)[1]), "=r"((r)[2]), "=r"((r)[3]) : "r"(addr))
#define CP16(dst, src) \
    asm volatile("cp.async.cg.shared.global [%0], [%1], 16;" :: "r"(dst), "l"(src))
#define CP_COMMIT() asm volatile("cp.async.commit_group;" ::: "memory")
#define CP_WAIT0()  asm volatile("cp.async.wait_group 0;" ::: "memory")
#define CP_WAIT1()  asm volatile("cp.async.wait_group 1;" ::: "memory")

__device__ __forceinline__ uint32_t smem_u32(const void* p) {
    return (uint32_t)__cvta_generic_to_shared(p);
}
__device__ __forceinline__ uint32_t h2u(__half2 h) { return *(uint32_t*)&h; }

// ---- global scratch ----
__device__ __align__(16) __nv_bfloat16 g_qh[NB * NT * ND];
__device__ __align__(16) __nv_bfloat16 g_ql[NB * NT * ND];
__device__ __align__(16) __nv_bfloat16 g_kh[NB * NT * ND];
__device__ __align__(16) __nv_bfloat16 g_kl[NB * NT * ND];
__device__ __align__(16) __nv_bfloat16 g_vth[NB * ND * NT];
__device__ __align__(16) __nv_bfloat16 g_vtl[NB * ND * NT];
__device__ __align__(16) __half g_Bh[192 * NC];
__device__ __align__(16) float2 g_rope[NT * 32];

// ---------------------------------------------------------------------------
// W conversion (fp16 single) + RoPE table fill
// ---------------------------------------------------------------------------
__global__ __launch_bounds__(256) void wconv_kernel(
    const float* __restrict__ Wq, const float* __restrict__ Wk, const float* __restrict__ Wv)
{
    int idx = blockIdx.x * 256 + threadIdx.x;
    if (idx < NT * 32) {
        int t = idx >> 5, pi = idx & 31;
        float freq = expf((float)(2 * pi) * (-9.210340371976184f / (float)ND));
        float sv, cv;
        sincosf((float)t * freq, &sv, &cv);
        g_rope[idx] = make_float2(cv, sv);
    }
    int mat = idx / 49152;
    int r = idx - mat * 49152;
    int n = r / NC;
    int k = r - n * NC;
    const float* W = (mat == 0) ? Wq : (mat == 1) ? Wk : Wv;
    g_Bh[idx] = __float2half_rn(W[k * ND + n]);
}

// ---------------------------------------------------------------------------
// Fused QKV GEMM (fp16 2-term). M=64/CTA, N=192. grid 512, 256 threads.
// 3-stage cp.async B ring (wait_group 1), 2-buffer A convert, reg-prefetched x.
// smem layout: AH[2] @0/5120, AL[2] @10240/15360, B[3] @20480+15360*s. 66560 B.
// B copy = 3 x CP16/thread (768 chunks = full 192 rows).
// ---------------------------------------------------------------------------
#define QS_AH0 0
#define QS_AL0 10240
#define QS_B0  20480
#define QS_BSZ 15360
#define QKV_SMEM 66560

__global__ __launch_bounds__(256, 2) void qkv_mma(const float* __restrict__ x)
{
    extern __shared__ __align__(16) char sm[];
    const uint32_t smb = smem_u32(sm);

    const int tid = threadIdx.x;
    const int lane = tid & 31, w = tid >> 5;
    const int warpM = w & 1, warpN = w >> 1;
    const int g = lane >> 2, qd = lane & 3;
    const int m0 = blockIdx.x * 64;

    float acc[2][6][4];
#pragma unroll
    for (int mt = 0; mt < 2; mt++)
#pragma unroll
        for (int nt = 0; nt < 6; nt++)
#pragma unroll
            for (int i = 0; i < 4; i++) acc[mt][nt][i] = 0.f;

    const int am = tid >> 2, kq = tid & 3;
    const float* xrow = x + (size_t)(m0 + am) * NC + kq * 8;
    const uint32_t asoff = am * 80 + kq * 16;

    const uint32_t aoff = (uint32_t)((warpM * 32 + (lane & 15)) * 80 + ((lane >> 4) << 4));
    const uint32_t boff = (uint32_t)((warpN * 48 + (lane & 7) + ((lane >> 4) << 3)) * 80
                                     + (((lane >> 3) & 1) << 4));

    // B copy mapping: 3 chunks/thread covering 192 rows x 4 quads
    int brow_[3], bq_[3];
#pragma unroll
    for (int i = 0; i < 3; i++) {
        int id = i * 256 + tid;
        brow_[i] = id >> 2;
        bq_[i] = id & 3;
    }

    // prologue: A(0) -> regs; B(0), B(1) -> stages 0,1 (two groups)
    float4 rA[2][2];
    rA[0][0] = *(const float4*)(xrow);
    rA[0][1] = *(const float4*)(xrow + 4);
#pragma unroll
    for (int i = 0; i < 3; i++)
        CP16(smb + QS_B0 + brow_[i] * 80 + bq_[i] * 16,
             (const char*)(g_Bh + brow_[i] * NC) + bq_[i] * 16);
    CP_COMMIT();
#pragma unroll
    for (int i = 0; i < 3; i++)
        CP16(smb + QS_B0 + QS_BSZ + brow_[i] * 80 + bq_[i] * 16,
             (const char*)(g_Bh + brow_[i] * NC + 32) + bq_[i] * 16);
    CP_COMMIT();

    for (int c = 0; c < 24; c++) {
        const int sa = c & 1;          // A buffer
        const int sb0 = c % 3;         // B stage holding B(c)
        const uint32_t ahb = smb + QS_AH0 + sa * 5120;
        const uint32_t bbb = smb + QS_B0 + sb0 * QS_BSZ;

        if (c + 1 < 24) {
            rA[(c + 1) & 1][0] = *(const float4*)(xrow + (c + 1) * 32);
            rA[(c + 1) & 1][1] = *(const float4*)(xrow + (c + 1) * 32 + 4);
        }
        {
            float4 f0 = rA[c & 1][0], f1 = rA[c & 1][1];
            __half2 h0 = __floats2half2_rn(f0.x, f0.y);
            __half2 h1 = __floats2half2_rn(f0.z, f0.w);
            __half2 h2 = __floats2half2_rn(f1.x, f1.y);
            __half2 h3 = __floats2half2_rn(f1.z, f1.w);
            __half2 l0 = __floats2half2_rn(f0.x - __low2float(h0), f0.y - __high2float(h0));
            __half2 l1 = __floats2half2_rn(f0.z - __low2float(h1), f0.w - __high2float(h1));
            __half2 l2 = __floats2half2_rn(f1.x - __low2float(h2), f1.y - __high2float(h2));
            __half2 l3 = __floats2half2_rn(f1.z - __low2float(h3), f1.w - __high2float(h3));
            char* base = sm + sa * 5120;
            *(uint4*)(base + QS_AH0 + asoff) = make_uint4(h2u(h0), h2u(h1), h2u(h2), h2u(h3));
            *(uint4*)(base + QS_AL0 + asoff) = make_uint4(h2u(l0), h2u(l1), h2u(l2), h2u(l3));
        }

        // B(c) must be complete; B(c+1) may stay in flight.
        if (c < 22) { CP_WAIT1(); } else { CP_WAIT0(); }
        __syncthreads();

        if (c + 2 < 24) {   // B(c+2) -> stage (c+2)%3 (stage reads finished pre-sync)
            const uint32_t nst = smb + QS_B0 + ((c + 2) % 3) * QS_BSZ;
#pragma unroll
            for (int i = 0; i < 3; i++)
                CP16(nst + brow_[i] * 80 + bq_[i] * 16,
                     (const char*)(g_Bh + brow_[i] * NC + (c + 2) * 32) + bq_[i] * 16);
            CP_COMMIT();
        }

        // ---- MMA (fp16 2-term, interleaved accumulators) ----
#pragma unroll
        for (int ks = 0; ks < 2; ks++) {
            uint32_t ah[2][4], al[2][4];
#pragma unroll
            for (int mt = 0; mt < 2; mt++) {
                uint32_t a = ahb + aoff + mt * (16 * 80) + ks * 32;
                LDM4(ah[mt], a);
                LDM4(al[mt], a + (QS_AL0 - QS_AH0));
            }
#pragma unroll
            for (int p = 0; p < 3; p++) {
                uint32_t bh4[4];
                uint32_t ba = bbb + boff + p * (16 * 80) + ks * 32;
                LDM4(bh4, ba);
                mma_f16(acc[0][2 * p],     ah[0], bh4);
                mma_f16(acc[0][2 * p + 1], ah[0], bh4 + 2);
                mma_f16(acc[1][2 * p],     ah[1], bh4);
                mma_f16(acc[1][2 * p + 1], ah[1], bh4 + 2);
                mma_f16(acc[0][2 * p],     al[0], bh4);
                mma_f16(acc[0][2 * p + 1], al[0], bh4 + 2);
                mma_f16(acc[1][2 * p],     al[1], bh4);
                mma_f16(acc[1][2 * p + 1], al[1], bh4 + 2);
            }
        }
    }
    __syncthreads();

    // ---- epilogue (unchanged) ----
    float* vsm = (float*)sm;   // [64 d][68 m]
#pragma unroll
    for (int nt = 0; nt < 6; nt++) {
        int col0 = warpN * 48 + nt * 8 + qd * 2;
        if (col0 < 128) {
            int mat = col0 >> 6;
            int cin = col0 & 63;
            float sc = (mat == 0) ? 0.03608439182435161f : 1.0f;
            __nv_bfloat16* dstH = (mat == 0) ? g_qh : g_kh;
            __nv_bfloat16* dstL = (mat == 0) ? g_ql : g_kl;
            int pi = cin >> 1;
            int chunk = cin >> 3;
            int bw = (cin & 7) * 2;
#pragma unroll
            for (int mt = 0; mt < 2; mt++) {
#pragma unroll
                for (int half = 0; half < 2; half++) {
                    int ml = warpM * 32 + mt * 16 + g + half * 8;
                    int r = m0 + ml;
                    float2 cs = g_rope[((r & (NT - 1)) << 5) + pi];
                    float e = acc[mt][nt][half * 2], o = acc[mt][nt][half * 2 + 1];
                    float re = (e * cs.x - o * cs.y) * sc;
                    float ro = (e * cs.y + o * cs.x) * sc;
                    uint32_t h = pack_bf2(re, ro);
                    uint32_t l = pack_bf2(re - lo_bf(h), ro - hi_bf(h));
                    size_t byte = (size_t)r * 128 + 16 * (chunk ^ (ml & 7)) + bw;
                    *(uint32_t*)((char*)dstH + byte) = h;
                    *(uint32_t*)((char*)dstL + byte) = l;
                }
            }
        } else {
            int cin = col0 & 63;
#pragma unroll
            for (int mt = 0; mt < 2; mt++) {
#pragma unroll
                for (int half = 0; half < 2; half++) {
                    int ml = warpM * 32 + mt * 16 + g + half * 8;
                    vsm[cin * 68 + ml]       = acc[mt][nt][half * 2];
                    vsm[(cin + 1) * 68 + ml] = acc[mt][nt][half * 2 + 1];
                }
            }
        }
    }
    __syncthreads();
    {
        const int bb = m0 >> 10;
        const int t0l = m0 & (NT - 1);
#pragma unroll
        for (int i = 0; i < 8; i++) {
            int idx = tid + i * 256;
            int d = idx >> 5;
            int pr = idx & 31;
            int tl = pr * 2;
            float v0 = vsm[d * 68 + tl];
            float v1 = vsm[d * 68 + tl + 1];
            uint32_t h = pack_bf2(v0, v1);
            uint32_t l = pack_bf2(v0 - lo_bf(h), v1 - hi_bf(h));
            size_t byte = ((size_t)(bb * 64 + d) * 1024 + t0l) * 2
                        + 16 * ((tl >> 3) ^ (d & 7)) + (tl & 7) * 2;
            *(uint32_t*)((char*)g_vth + byte) = h;
            *(uint32_t*)((char*)g_vtl + byte) = l;
        }
    }
}

// ---------------------------------------------------------------------------
// Flash attention: r7 version verbatim (~41us, at legacy tensor-pipe peak).
// ---------------------------------------------------------------------------
#define AQ_H 0
#define AQ_L 16384
#define A_ST 32768
#define A_STAGE 32768
#define ATTN_SMEM 98304

__global__ __launch_bounds__(256, 2) void attn_mma(float* __restrict__ out)
{
    extern __shared__ __align__(16) char sm[];
    const uint32_t smb = smem_u32(sm);

    const int tid = threadIdx.x;
    const int lane = tid & 31, w = tid >> 5;
    const int g = lane >> 2, qd = lane & 3;
    const int bid = (int)blockIdx.x;
    const int rk = (bid < 148) ? bid : 403 - bid;
    const int qt = 7 - (rk >> 5);
    const int b = rk & 31;
    const int q0 = qt * 128;
    const int jmax = 2 * qt + 1;

    {
        const char* qH = (const char*)(g_qh + (size_t)(b * NT + q0) * ND);
        const char* qL = (const char*)(g_ql + (size_t)(b * NT + q0) * ND);
#pragma unroll
        for (int i = 0; i < 4; i++) {
            int idx = tid + i * 256;
            CP16(smb + AQ_H + idx * 16, qH + idx * 16);
            CP16(smb + AQ_L + idx * 16, qL + idx * 16);
        }
        const char* kH = (const char*)(g_kh + (size_t)(b * NT) * ND);
        const char* kL = (const char*)(g_kl + (size_t)(b * NT) * ND);
#pragma unroll
        for (int i = 0; i < 2; i++) {
            int idx = tid + i * 256;
            CP16(smb + A_ST + idx * 16, kH + idx * 16);
            CP16(smb + A_ST + 8192 + idx * 16, kL + idx * 16);
            int d = idx >> 3, c = idx & 7;
            size_t vb = (size_t)(b * 64 + d) * 2048 + c * 16;
            CP16(smb + A_ST + 16384 + idx * 16, (const char*)g_vth + vb);
            CP16(smb + A_ST + 24576 + idx * 16, (const char*)g_vtl + vb);
        }
        CP_COMMIT();
    }

    float o[8][4];
    float m_r[2], l_r[2];
#pragma unroll
    for (int nd = 0; nd < 8; nd++)
#pragma unroll
        for (int i = 0; i < 4; i++) o[nd][i] = 0.f;
    m_r[0] = m_r[1] = -INFINITY;
    l_r[0] = l_r[1] = 0.f;

    const uint32_t aoffQ = (uint32_t)((w * 16 + (lane & 15)) * 128);
    const uint32_t browB = (uint32_t)((lane & 7) + ((lane >> 4) << 3));
    const int lx = lane & 7, lb = (lane >> 3) & 1;
    const int rmax = q0 + w * 16 + 15;

    CP_WAIT0();
    __syncthreads();

    for (int jt = 0; jt <= jmax; jt++) {
        const int s = jt & 1;
        const uint32_t stb = smb + A_ST + s * A_STAGE;

        if (jt > 0) { CP_WAIT0(); __syncthreads(); }

        if (jt < jmax) {
            const int kvn = (jt + 1) * 64;
            const uint32_t nst = smb + A_ST + (s ^ 1) * A_STAGE;
            const char* kH = (const char*)(g_kh + (size_t)(b * NT + kvn) * ND);
            const char* kL = (const char*)(g_kl + (size_t)(b * NT + kvn) * ND);
#pragma unroll
            for (int i = 0; i < 2; i++) {
                int idx = tid + i * 256;
                CP16(nst + idx * 16, kH + idx * 16);
                CP16(nst + 8192 + idx * 16, kL + idx * 16);
                int d = idx >> 3, c = idx & 7;
                size_t vb = ((size_t)(b * 64 + d) * 1024 + kvn) * 2 + c * 16;
                CP16(nst + 16384 + idx * 16, (const char*)g_vth + vb);
                CP16(nst + 24576 + idx * 16, (const char*)g_vtl + vb);
            }
            CP_COMMIT();
        }

        if (jt * 64 > rmax) continue;
        const bool diag = (jt >= 2 * qt);

        float s_[8][4];
#pragma unroll
        for (int nt = 0; nt < 8; nt++)
#pragma unroll
            for (int i = 0; i < 4; i++) s_[nt][i] = 0.f;

#pragma unroll
        for (int ks = 0; ks < 4; ks++) {
            uint32_t qh4[4], ql4[4];
            uint32_t chQ = (uint32_t)(((2 * ks + (lane >> 4)) ^ lx) * 16);
            LDM4(qh4, smb + AQ_H + aoffQ + chQ);
            LDM4(ql4, smb + AQ_L + aoffQ + chQ);
            uint32_t ch = (uint32_t)(((2 * ks + lb) ^ lx) * 16);
#pragma unroll
            for (int ntp = 0; ntp < 4; ntp++) {
                if (diag && jt * 64 + ntp * 16 > rmax) continue;
                uint32_t bh4[4], bl4[4];
                uint32_t ba = stb + (ntp * 16 + browB) * 128 + ch;
                LDM4(bh4, ba);
                LDM4(bl4, ba + 8192);
                mma16816(s_[2 * ntp], qh4, bh4);
                mma16816(s_[2 * ntp], qh4, bl4);
                mma16816(s_[2 * ntp], ql4, bh4);
                mma16816(s_[2 * ntp + 1], qh4, bh4 + 2);
                mma16816(s_[2 * ntp + 1], qh4, bl4 + 2);
                mma16816(s_[2 * ntp + 1], ql4, bh4 + 2);
            }
        }

        if (diag) {
#pragma unroll
            for (int nt = 0; nt < 8; nt++) {
                int col = jt * 64 + nt * 8 + qd * 2;
#pragma unroll
                for (int half = 0; half < 2; half++) {
                    int row = q0 + w * 16 + g + half * 8;
                    if (col > row)     s_[nt][half * 2]     = -INFINITY;
                    if (col + 1 > row) s_[nt][half * 2 + 1] = -INFINITY;
                }
            }
        }

#pragma unroll
        for (int half = 0; half < 2; half++) {
            float mx = -INFINITY;
#pragma unroll
            for (int nt = 0; nt < 8; nt++)
                mx = fmaxf(mx, fmaxf(s_[nt][half * 2], s_[nt][half * 2 + 1]));
            mx = fmaxf(mx, __shfl_xor_sync(0xffffffffu, mx, 1));
            mx = fmaxf(mx, __shfl_xor_sync(0xffffffffu, mx, 2));
            float mn = fmaxf(m_r[half], mx);
            float alpha = __expf(m_r[half] - mn);
            m_r[half] = mn;
            float sum = 0.f;
#pragma unroll
            for (int nt = 0; nt < 8; nt++) {
                float p0 = __expf(s_[nt][half * 2] - mn);
                float p1 = __expf(s_[nt][half * 2 + 1] - mn);
                s_[nt][half * 2] = p0;
                s_[nt][half * 2 + 1] = p1;
                sum += p0 + p1;
            }
            sum += __shfl_xor_sync(0xffffffffu, sum, 1);
            sum += __shfl_xor_sync(0xffffffffu, sum, 2);
            l_r[half] = l_r[half] * alpha + sum;
#pragma unroll
            for (int nd = 0; nd < 8; nd++) {
                o[nd][half * 2] *= alpha;
                o[nd][half * 2 + 1] *= alpha;
            }
        }

#pragma unroll
        for (int ks = 0; ks < 4; ks++) {
            if (diag && jt * 64 + ks * 16 > rmax) continue;
            uint32_t ah[4], al[4];
            ah[0] = pack_bf2(s_[2 * ks][0], s_[2 * ks][1]);
            ah[1] = pack_bf2(s_[2 * ks][2], s_[2 * ks][3]);
            ah[2] = pack_bf2(s_[2 * ks + 1][0], s_[2 * ks + 1][1]);
            ah[3] = pack_bf2(s_[2 * ks + 1][2], s_[2 * ks + 1][3]);
            al[0] = pack_bf2(s_[2 * ks][0] - lo_bf(ah[0]), s_[2 * ks][1] - hi_bf(ah[0]));
            al[1] = pack_bf2(s_[2 * ks][2] - lo_bf(ah[1]), s_[2 * ks][3] - hi_bf(ah[1]));
            al[2] = pack_bf2(s_[2 * ks + 1][0] - lo_bf(ah[2]), s_[2 * ks + 1][1] - hi_bf(ah[2]));
            al[3] = pack_bf2(s_[2 * ks + 1][2] - lo_bf(ah[3]), s_[2 * ks + 1][3] - hi_bf(ah[3]));
            uint32_t ch = (uint32_t)(((2 * ks + lb) ^ lx) * 16);
#pragma unroll
            for (int ntp = 0; ntp < 4; ntp++) {
                uint32_t bh4[4], bl4[4];
                uint32_t ba = stb + 16384 + (ntp * 16 + browB) * 128 + ch;
                LDM4(bh4, ba);
                LDM4(bl4, ba + 8192);
                mma16816(o[2 * ntp], ah, bh4);
                mma16816(o[2 * ntp], ah, bl4);
                mma16816(o[2 * ntp], al, bh4);
                mma16816(o[2 * ntp + 1], ah, bh4 + 2);
                mma16816(o[2 * ntp + 1], ah, bl4 + 2);
                mma16816(o[2 * ntp + 1], al, bh4 + 2);
            }
        }
    }

    float inv0 = 1.f / l_r[0];
    float inv1 = 1.f / l_r[1];
    int row0 = b * NT + q0 + w * 16 + g;
#pragma unroll
    for (int nd = 0; nd < 8; nd++) {
        int d = nd * 8 + qd * 2;
        *(float2*)(out + (size_t)row0 * ND + d) =
            make_float2(o[nd][0] * inv0, o[nd][1] * inv0);
        *(float2*)(out + (size_t)(row0 + 8) * ND + d) =
            make_float2(o[nd][2] * inv1, o[nd][3] * inv1);
    }
}

extern "C" void kernel_launch(void* const* d_in, const int* in_sizes, int n_in,
                              void* d_out, int out_size) {
    (void)in_sizes; (void)n_in; (void)out_size;
    const float* x  = (const float*)d_in[0];
    const float* Wq = (const float*)d_in[1];
    const float* Wk = (const float*)d_in[2];
    const float* Wv = (const float*)d_in[3];
    float* out = (float*)d_out;

    cudaFuncSetAttribute(qkv_mma, cudaFuncAttributeMaxDynamicSharedMemorySize, QKV_SMEM);
    cudaFuncSetAttribute(attn_mma, cudaFuncAttributeMaxDynamicSharedMemorySize, ATTN_SMEM);

    wconv_kernel<<<576, 256>>>(Wq, Wk, Wv);
    qkv_mma<<<512, 256, QKV_SMEM>>>(x);
    attn_mma<<<256, 256, ATTN_SMEM>>>(out);
}

// round 16
// speedup vs baseline: 1.2304x; 1.2304x over previous
#include <cuda_runtime.h>
#include <cuda_bf16.h>
#include <cuda_fp16.h>
#include <math.h>
#include <cstdint>

#define NB 32
#define NT 1024
#define NC 768
#define ND 64

// ---- helpers ----
__device__ __forceinline__ uint32_t pack_bf2(float lo, float hi) {
    uint32_t r; asm("cvt.rn.bf16x2.f32 %0, %1, %2;" : "=r"(r) : "f"(hi), "f"(lo)); return r;
}
__device__ __forceinline__ float lo_bf(uint32_t h) { return __uint_as_float(h << 16); }
__device__ __forceinline__ float hi_bf(uint32_t h) { return __uint_as_float(h & 0xffff0000u); }

__device__ __forceinline__ void mma16816(float* c, const uint32_t* a, const uint32_t* b) {
    asm volatile(
        "mma.sync.aligned.m16n8k16.row.col.f32.bf16.bf16.f32 "
        "{%0,%1,%2,%3}, {%4,%5,%6,%7}, {%8,%9}, {%0,%1,%2,%3};"
        : "+f"(c[0]), "+f"(c[1]), "+f"(c[2]), "+f"(c[3])
        : "r"(a[0]), "r"(a[1]), "r"(a[2]), "r"(a[3]), "r"(b[0]), "r"(b[1]));
}
__device__ __forceinline__ void mma_f16(float* c, const uint32_t* a, const uint32_t* b) {
    asm volatile(
        "mma.sync.aligned.m16n8k16.row.col.f32.f16.f16.f32 "
        "{%0,%1,%2,%3}, {%4,%5,%6,%7}, {%8,%9}, {%0,%1,%2,%3};"
        : "+f"(c[0]), "+f"(c[1]), "+f"(c[2]), "+f"(c[3])
        : "r"(a[0]), "r"(a[1]), "r"(a[2]), "r"(a[3]), "r"(b[0]), "r"(b[1]));
}
#define LDM4(r, addr) \
    asm volatile("ldmatrix.sync.aligned.m8n8.x4.shared.b16 {%0,%1,%2,%3}, [%4];" \
        : "=r"((r)[0]), "=r"((r)[1]), "=r"((r)[2]), "=r"((r)[3]) : "r"(addr))
#define CP16(dst, src) \
    asm volatile("cp.async.cg.shared.global [%0], [%1], 16;" :: "r"(dst), "l"(src))
#define CP_COMMIT() asm volatile("cp.async.commit_group;" ::: "memory")
#define CP_WAIT0()  asm volatile("cp.async.wait_group 0;" ::: "memory")

__device__ __forceinline__ uint32_t smem_u32(const void* p) {
    return (uint32_t)__cvta_generic_to_shared(p);
}
__device__ __forceinline__ uint32_t h2u(__half2 h) { return *(uint32_t*)&h; }

// ---- global scratch ----
__device__ __align__(16) __nv_bfloat16 g_qh[NB * NT * ND];
__device__ __align__(16) __nv_bfloat16 g_ql[NB * NT * ND];
__device__ __align__(16) __nv_bfloat16 g_kh[NB * NT * ND];
__device__ __align__(16) __nv_bfloat16 g_kl[NB * NT * ND];
__device__ __align__(16) __nv_bfloat16 g_vth[NB * ND * NT];
__device__ __align__(16) __nv_bfloat16 g_vtl[NB * ND * NT];
__device__ __align__(16) __half g_Bh[192 * NC];
__device__ __align__(16) float2 g_rope[NT * 32];

// ---------------------------------------------------------------------------
// W conversion (fp16 single) + RoPE table fill
// ---------------------------------------------------------------------------
__global__ __launch_bounds__(256) void wconv_kernel(
    const float* __restrict__ Wq, const float* __restrict__ Wk, const float* __restrict__ Wv)
{
    int idx = blockIdx.x * 256 + threadIdx.x;
    if (idx < NT * 32) {
        int t = idx >> 5, pi = idx & 31;
        float freq = expf((float)(2 * pi) * (-9.210340371976184f / (float)ND));
        float sv, cv;
        sincosf((float)t * freq, &sv, &cv);
        g_rope[idx] = make_float2(cv, sv);
    }
    int mat = idx / 49152;
    int r = idx - mat * 49152;
    int n = r / NC;
    int k = r - n * NC;
    const float* W = (mat == 0) ? Wq : (mat == 1) ? Wk : Wv;
    g_Bh[idx] = __float2half_rn(W[k * ND + n]);
}

// ---------------------------------------------------------------------------
// Fused QKV GEMM (fp16 2-term). M=64/CTA, N=192, K-chunk 64 (12 iterations).
// grid 512, 256 threads. 2-stage cp.async B; single-buffer A reg prefetch.
// Pitch 144 B rows (conflict-free LDSM). smem 92160 B, 2 CTAs/SM.
//   AH: sa*9216 (0, 9216); AL: 18432 + sa*9216; B: 36864 + stage*27648.
// ---------------------------------------------------------------------------
#define QK_AH 0
#define QK_AL 18432
#define QK_B  36864
#define QK_ABUF 9216
#define QK_BSZ 27648
#define QKV_SMEM 92160

__global__ __launch_bounds__(256, 2) void qkv_mma(const float* __restrict__ x)
{
    extern __shared__ __align__(16) char sm[];
    const uint32_t smb = smem_u32(sm);

    const int tid = threadIdx.x;
    const int lane = tid & 31, w = tid >> 5;
    const int warpM = w & 1, warpN = w >> 1;
    const int g = lane >> 2, qd = lane & 3;
    const int m0 = blockIdx.x * 64;

    float acc[2][6][4];
#pragma unroll
    for (int mt = 0; mt < 2; mt++)
#pragma unroll
        for (int nt = 0; nt < 6; nt++)
#pragma unroll
            for (int i = 0; i < 4; i++) acc[mt][nt][i] = 0.f;

    // A mapping: row = tid>>2 (0..63), 16-float section kq = tid&3
    const int am = tid >> 2, kq = tid & 3;
    const float* xrow = x + (size_t)(m0 + am) * NC + kq * 16;
    const uint32_t asoff = am * 144 + kq * 32;

    // fragment offsets (pitch 144)
    const uint32_t aoff = (uint32_t)((warpM * 32 + (lane & 15)) * 144 + ((lane >> 4) << 4));
    const uint32_t boff = (uint32_t)((warpN * 48 + (lane & 7) + ((lane >> 4) << 3)) * 144
                                     + (((lane >> 3) & 1) << 4));

    // prologue: A(0) -> regs; B(0) -> stage 0
    float4 rA[4];
#pragma unroll
    for (int j = 0; j < 4; j++) rA[j] = *(const float4*)(xrow + j * 4);
#pragma unroll
    for (int i = 0; i < 6; i++) {
        int id = i * 256 + tid;
        int row = id >> 3, q = id & 7;
        CP16(smb + QK_B + row * 144 + q * 16, (const char*)(g_Bh + row * NC) + q * 16);
    }
    CP_COMMIT();

#pragma unroll 2
    for (int c = 0; c < 12; c++) {
        const int sa = c & 1;
        const uint32_t ahb = smb + QK_AH + sa * QK_ABUF;
        const uint32_t bbb = smb + QK_B + sa * QK_BSZ;

        // convert A(c) from regs -> smem buffer sa
        {
            uint32_t h[8], l[8];
#pragma unroll
            for (int j = 0; j < 4; j++) {
                float4 f = rA[j];
                __half2 hh0 = __floats2half2_rn(f.x, f.y);
                __half2 hh1 = __floats2half2_rn(f.z, f.w);
                __half2 ll0 = __floats2half2_rn(f.x - __low2float(hh0), f.y - __high2float(hh0));
                __half2 ll1 = __floats2half2_rn(f.z - __low2float(hh1), f.w - __high2float(hh1));
                h[2 * j] = h2u(hh0); h[2 * j + 1] = h2u(hh1);
                l[2 * j] = h2u(ll0); l[2 * j + 1] = h2u(ll1);
            }
            char* base = sm + sa * QK_ABUF;
            *(uint4*)(base + QK_AH + asoff)      = make_uint4(h[0], h[1], h[2], h[3]);
            *(uint4*)(base + QK_AH + asoff + 16) = make_uint4(h[4], h[5], h[6], h[7]);
            *(uint4*)(base + QK_AL + asoff)      = make_uint4(l[0], l[1], l[2], l[3]);
            *(uint4*)(base + QK_AL + asoff + 16) = make_uint4(l[4], l[5], l[6], l[7]);
        }
        // prefetch A(c+1) into regs (consumed next iteration's convert)
        if (c + 1 < 12) {
#pragma unroll
            for (int j = 0; j < 4; j++)
                rA[j] = *(const float4*)(xrow + (c + 1) * 64 + j * 4);
        }

        CP_WAIT0();          // B(c) arrived
        __syncthreads();     // STS visible; prev MMA done

        if (c + 1 < 12) {    // B(c+1) -> other stage; covered by this iter's MMA
            const uint32_t nst = smb + QK_B + (sa ^ 1) * QK_BSZ;
#pragma unroll
            for (int i = 0; i < 6; i++) {
                int id = i * 256 + tid;
                int row = id >> 3, q = id & 7;
                CP16(nst + row * 144 + q * 16,
                     (const char*)(g_Bh + row * NC + (c + 1) * 64) + q * 16);
            }
            CP_COMMIT();
        }

        // ---- MMA on stage sa (fp16 2-term, interleaved accumulators) ----
#pragma unroll
        for (int ks = 0; ks < 4; ks++) {
            uint32_t ah[2][4], al[2][4];
#pragma unroll
            for (int mt = 0; mt < 2; mt++) {
                uint32_t a = ahb + aoff + mt * (16 * 144) + ks * 32;
                LDM4(ah[mt], a);
                LDM4(al[mt], a + (QK_AL - QK_AH));
            }
#pragma unroll
            for (int p = 0; p < 3; p++) {
                uint32_t bh4[4];
                uint32_t ba = bbb + boff + p * (16 * 144) + ks * 32;
                LDM4(bh4, ba);
                mma_f16(acc[0][2 * p],     ah[0], bh4);
                mma_f16(acc[0][2 * p + 1], ah[0], bh4 + 2);
                mma_f16(acc[1][2 * p],     ah[1], bh4);
                mma_f16(acc[1][2 * p + 1], ah[1], bh4 + 2);
                mma_f16(acc[0][2 * p],     al[0], bh4);
                mma_f16(acc[0][2 * p + 1], al[0], bh4 + 2);
                mma_f16(acc[1][2 * p],     al[1], bh4);
                mma_f16(acc[1][2 * p + 1], al[1], bh4 + 2);
            }
        }
    }
    __syncthreads();

    // ---- epilogue (unchanged from r12) ----
    float* vsm = (float*)sm;   // [64 d][68 m]
#pragma unroll
    for (int nt = 0; nt < 6; nt++) {
        int col0 = warpN * 48 + nt * 8 + qd * 2;
        if (col0 < 128) {
            int mat = col0 >> 6;
            int cin = col0 & 63;
            float sc = (mat == 0) ? 0.03608439182435161f : 1.0f;
            __nv_bfloat16* dstH = (mat == 0) ? g_qh : g_kh;
            __nv_bfloat16* dstL = (mat == 0) ? g_ql : g_kl;
            int pi = cin >> 1;
            int chunk = cin >> 3;
            int bw = (cin & 7) * 2;
#pragma unroll
            for (int mt = 0; mt < 2; mt++) {
#pragma unroll
                for (int half = 0; half < 2; half++) {
                    int ml = warpM * 32 + mt * 16 + g + half * 8;
                    int r = m0 + ml;
                    float2 cs = g_rope[((r & (NT - 1)) << 5) + pi];
                    float e = acc[mt][nt][half * 2], o = acc[mt][nt][half * 2 + 1];
                    float re = (e * cs.x - o * cs.y) * sc;
                    float ro = (e * cs.y + o * cs.x) * sc;
                    uint32_t h = pack_bf2(re, ro);
                    uint32_t l = pack_bf2(re - lo_bf(h), ro - hi_bf(h));
                    size_t byte = (size_t)r * 128 + 16 * (chunk ^ (ml & 7)) + bw;
                    *(uint32_t*)((char*)dstH + byte) = h;
                    *(uint32_t*)((char*)dstL + byte) = l;
                }
            }
        } else {
            int cin = col0 & 63;
#pragma unroll
            for (int mt = 0; mt < 2; mt++) {
#pragma unroll
                for (int half = 0; half < 2; half++) {
                    int ml = warpM * 32 + mt * 16 + g + half * 8;
                    vsm[cin * 68 + ml]       = acc[mt][nt][half * 2];
                    vsm[(cin + 1) * 68 + ml] = acc[mt][nt][half * 2 + 1];
                }
            }
        }
    }
    __syncthreads();
    {
        const int bb = m0 >> 10;
        const int t0l = m0 & (NT - 1);
#pragma unroll
        for (int i = 0; i < 8; i++) {
            int idx = tid + i * 256;
            int d = idx >> 5;
            int pr = idx & 31;
            int tl = pr * 2;
            float v0 = vsm[d * 68 + tl];
            float v1 = vsm[d * 68 + tl + 1];
            uint32_t h = pack_bf2(v0, v1);
            uint32_t l = pack_bf2(v0 - lo_bf(h), v1 - hi_bf(h));
            size_t byte = ((size_t)(bb * 64 + d) * 1024 + t0l) * 2
                        + 16 * ((tl >> 3) ^ (d & 7)) + (tl & 7) * 2;
            *(uint32_t*)((char*)g_vth + byte) = h;
            *(uint32_t*)((char*)g_vtl + byte) = l;
        }
    }
}

// ---------------------------------------------------------------------------
// Flash attention: r7 version verbatim (~41us, at legacy tensor-pipe peak).
// ---------------------------------------------------------------------------
#define AQ_H 0
#define AQ_L 16384
#define A_ST 32768
#define A_STAGE 32768
#define ATTN_SMEM 98304

__global__ __launch_bounds__(256, 2) void attn_mma(float* __restrict__ out)
{
    extern __shared__ __align__(16) char sm[];
    const uint32_t smb = smem_u32(sm);

    const int tid = threadIdx.x;
    const int lane = tid & 31, w = tid >> 5;
    const int g = lane >> 2, qd = lane & 3;
    const int bid = (int)blockIdx.x;
    const int rk = (bid < 148) ? bid : 403 - bid;
    const int qt = 7 - (rk >> 5);
    const int b = rk & 31;
    const int q0 = qt * 128;
    const int jmax = 2 * qt + 1;

    {
        const char* qH = (const char*)(g_qh + (size_t)(b * NT + q0) * ND);
        const char* qL = (const char*)(g_ql + (size_t)(b * NT + q0) * ND);
#pragma unroll
        for (int i = 0; i < 4; i++) {
            int idx = tid + i * 256;
            CP16(smb + AQ_H + idx * 16, qH + idx * 16);
            CP16(smb + AQ_L + idx * 16, qL + idx * 16);
        }
        const char* kH = (const char*)(g_kh + (size_t)(b * NT) * ND);
        const char* kL = (const char*)(g_kl + (size_t)(b * NT) * ND);
#pragma unroll
        for (int i = 0; i < 2; i++) {
            int idx = tid + i * 256;
            CP16(smb + A_ST + idx * 16, kH + idx * 16);
            CP16(smb + A_ST + 8192 + idx * 16, kL + idx * 16);
            int d = idx >> 3, c = idx & 7;
            size_t vb = (size_t)(b * 64 + d) * 2048 + c * 16;
            CP16(smb + A_ST + 16384 + idx * 16, (const char*)g_vth + vb);
            CP16(smb + A_ST + 24576 + idx * 16, (const char*)g_vtl + vb);
        }
        CP_COMMIT();
    }

    float o[8][4];
    float m_r[2], l_r[2];
#pragma unroll
    for (int nd = 0; nd < 8; nd++)
#pragma unroll
        for (int i = 0; i < 4; i++) o[nd][i] = 0.f;
    m_r[0] = m_r[1] = -INFINITY;
    l_r[0] = l_r[1] = 0.f;

    const uint32_t aoffQ = (uint32_t)((w * 16 + (lane & 15)) * 128);
    const uint32_t browB = (uint32_t)((lane & 7) + ((lane >> 4) << 3));
    const int lx = lane & 7, lb = (lane >> 3) & 1;
    const int rmax = q0 + w * 16 + 15;

    CP_WAIT0();
    __syncthreads();

    for (int jt = 0; jt <= jmax; jt++) {
        const int s = jt & 1;
        const uint32_t stb = smb + A_ST + s * A_STAGE;

        if (jt > 0) { CP_WAIT0(); __syncthreads(); }

        if (jt < jmax) {
            const int kvn = (jt + 1) * 64;
            const uint32_t nst = smb + A_ST + (s ^ 1) * A_STAGE;
            const char* kH = (const char*)(g_kh + (size_t)(b * NT + kvn) * ND);
            const char* kL = (const char*)(g_kl + (size_t)(b * NT + kvn) * ND);
#pragma unroll
            for (int i = 0; i < 2; i++) {
                int idx = tid + i * 256;
                CP16(nst + idx * 16, kH + idx * 16);
                CP16(nst + 8192 + idx * 16, kL + idx * 16);
                int d = idx >> 3, c = idx & 7;
                size_t vb = ((size_t)(b * 64 + d) * 1024 + kvn) * 2 + c * 16;
                CP16(nst + 16384 + idx * 16, (const char*)g_vth + vb);
                CP16(nst + 24576 + idx * 16, (const char*)g_vtl + vb);
            }
            CP_COMMIT();
        }

        if (jt * 64 > rmax) continue;
        const bool diag = (jt >= 2 * qt);

        float s_[8][4];
#pragma unroll
        for (int nt = 0; nt < 8; nt++)
#pragma unroll
            for (int i = 0; i < 4; i++) s_[nt][i] = 0.f;

#pragma unroll
        for (int ks = 0; ks < 4; ks++) {
            uint32_t qh4[4], ql4[4];
            uint32_t chQ = (uint32_t)(((2 * ks + (lane >> 4)) ^ lx) * 16);
            LDM4(qh4, smb + AQ_H + aoffQ + chQ);
            LDM4(ql4, smb + AQ_L + aoffQ + chQ);
            uint32_t ch = (uint32_t)(((2 * ks + lb) ^ lx) * 16);
#pragma unroll
            for (int ntp = 0; ntp < 4; ntp++) {
                if (diag && jt * 64 + ntp * 16 > rmax) continue;
                uint32_t bh4[4], bl4[4];
                uint32_t ba = stb + (ntp * 16 + browB) * 128 + ch;
                LDM4(bh4, ba);
                LDM4(bl4, ba + 8192);
                mma16816(s_[2 * ntp], qh4, bh4);
                mma16816(s_[2 * ntp], qh4, bl4);
                mma16816(s_[2 * ntp], ql4, bh4);
                mma16816(s_[2 * ntp + 1], qh4, bh4 + 2);
                mma16816(s_[2 * ntp + 1], qh4, bl4 + 2);
                mma16816(s_[2 * ntp + 1], ql4, bh4 + 2);
            }
        }

        if (diag) {
#pragma unroll
            for (int nt = 0; nt < 8; nt++) {
                int col = jt * 64 + nt * 8 + qd * 2;
#pragma unroll
                for (int half = 0; half < 2; half++) {
                    int row = q0 + w * 16 + g + half * 8;
                    if (col > row)     s_[nt][half * 2]     = -INFINITY;
                    if (col + 1 > row) s_[nt][half * 2 + 1] = -INFINITY;
                }
            }
        }

#pragma unroll
        for (int half = 0; half < 2; half++) {
            float mx = -INFINITY;
#pragma unroll
            for (int nt = 0; nt < 8; nt++)
                mx = fmaxf(mx, fmaxf(s_[nt][half * 2], s_[nt][half * 2 + 1]));
            mx = fmaxf(mx, __shfl_xor_sync(0xffffffffu, mx, 1));
            mx = fmaxf(mx, __shfl_xor_sync(0xffffffffu, mx, 2));
            float mn = fmaxf(m_r[half], mx);
            float alpha = __expf(m_r[half] - mn);
            m_r[half] = mn;
            float sum = 0.f;
#pragma unroll
            for (int nt = 0; nt < 8; nt++) {
                float p0 = __expf(s_[nt][half * 2] - mn);
                float p1 = __expf(s_[nt][half * 2 + 1] - mn);
                s_[nt][half * 2] = p0;
                s_[nt][half * 2 + 1] = p1;
                sum += p0 + p1;
            }
            sum += __shfl_xor_sync(0xffffffffu, sum, 1);
            sum += __shfl_xor_sync(0xffffffffu, sum, 2);
            l_r[half] = l_r[half] * alpha + sum;
#pragma unroll
            for (int nd = 0; nd < 8; nd++) {
                o[nd][half * 2] *= alpha;
                o[nd][half * 2 + 1] *= alpha;
            }
        }

#pragma unroll
        for (int ks = 0; ks < 4; ks++) {
            if (diag && jt * 64 + ks * 16 > rmax) continue;
            uint32_t ah[4], al[4];
            ah[0] = pack_bf2(s_[2 * ks][0], s_[2 * ks][1]);
            ah[1] = pack_bf2(s_[2 * ks][2], s_[2 * ks][3]);
            ah[2] = pack_bf2(s_[2 * ks + 1][0], s_[2 * ks + 1][1]);
            ah[3] = pack_bf2(s_[2 * ks + 1][2], s_[2 * ks + 1][3]);
            al[0] = pack_bf2(s_[2 * ks][0] - lo_bf(ah[0]), s_[2 * ks][1] - hi_bf(ah[0]));
            al[1] = pack_bf2(s_[2 * ks][2] - lo_bf(ah[1]), s_[2 * ks][3] - hi_bf(ah[1]));
            al[2] = pack_bf2(s_[2 * ks + 1][0] - lo_bf(ah[2]), s_[2 * ks + 1][1] - hi_bf(ah[2]));
            al[3] = pack_bf2(s_[2 * ks + 1][2] - lo_bf(ah[3]), s_[2 * ks + 1][3] - hi_bf(ah[3]));
            uint32_t ch = (uint32_t)(((2 * ks + lb) ^ lx) * 16);
#pragma unroll
            for (int ntp = 0; ntp < 4; ntp++) {
                uint32_t bh4[4], bl4[4];
                uint32_t ba = stb + 16384 + (ntp * 16 + browB) * 128 + ch;
                LDM4(bh4, ba);
                LDM4(bl4, ba + 8192);
                mma16816(o[2 * ntp], ah, bh4);
                mma16816(o[2 * ntp], ah, bl4);
                mma16816(o[2 * ntp], al, bh4);
                mma16816(o[2 * ntp + 1], ah, bh4 + 2);
                mma16816(o[2 * ntp + 1], ah, bl4 + 2);
                mma16816(o[2 * ntp + 1], al, bh4 + 2);
            }
        }
    }

    float inv0 = 1.f / l_r[0];
    float inv1 = 1.f / l_r[1];
    int row0 = b * NT + q0 + w * 16 + g;
#pragma unroll
    for (int nd = 0; nd < 8; nd++) {
        int d = nd * 8 + qd * 2;
        *(float2*)(out + (size_t)row0 * ND + d) =
            make_float2(o[nd][0] * inv0, o[nd][1] * inv0);
        *(float2*)(out + (size_t)(row0 + 8) * ND + d) =
            make_float2(o[nd][2] * inv1, o[nd][3] * inv1);
    }
}

extern "C" void kernel_launch(void* const* d_in, const int* in_sizes, int n_in,
                              void* d_out, int out_size) {
    (void)in_sizes; (void)n_in; (void)out_size;
    const float* x  = (const float*)d_in[0];
    const float* Wq = (const float*)d_in[1];
    const float* Wk = (const float*)d_in[2];
    const float* Wv = (const float*)d_in[3];
    float* out = (float*)d_out;

    cudaFuncSetAttribute(qkv_mma, cudaFuncAttributeMaxDynamicSharedMemorySize, QKV_SMEM);
    cudaFuncSetAttribute(attn_mma, cudaFuncAttributeMaxDynamicSharedMemorySize, ATTN_SMEM);

    wconv_kernel<<<576, 256>>>(Wq, Wk, Wv);
    qkv_mma<<<512, 256, QKV_SMEM>>>(x);
    attn_mma<<<256, 256, ATTN_SMEM>>>(out);
}

// round 17
// speedup vs baseline: 1.3686x; 1.1124x over previous
#include <cuda_runtime.h>
#include <cuda_bf16.h>
#include <cuda_fp16.h>
#include <math.h>
#include <cstdint>

#define NB 32
#define NT 1024
#define NC 768
#define ND 64

// ---- helpers ----
__device__ __forceinline__ void mma_f16(float* c, const uint32_t* a, const uint32_t* b) {
    asm volatile(
        "mma.sync.aligned.m16n8k16.row.col.f32.f16.f16.f32 "
        "{%0,%1,%2,%3}, {%4,%5,%6,%7}, {%8,%9}, {%0,%1,%2,%3};"
        : "+f"(c[0]), "+f"(c[1]), "+f"(c[2]), "+f"(c[3])
        : "r"(a[0]), "r"(a[1]), "r"(a[2]), "r"(a[3]), "r"(b[0]), "r"(b[1]));
}
#define LDM4(r, addr) \
    asm volatile("ldmatrix.sync.aligned.m8n8.x4.shared.b16 {%0,%1,%2,%3}, [%4];" \
        : "=r"((r)[0]), "=r"((r)[1]), "=r"((r)[2]), "=r"((r)[3]) : "r"(addr))
#define CP16(dst, src) \
    asm volatile("cp.async.cg.shared.global [%0], [%1], 16;" :: "r"(dst), "l"(src))
#define CP_COMMIT() asm volatile("cp.async.commit_group;" ::: "memory")
#define CP_WAIT0()  asm volatile("cp.async.wait_group 0;" ::: "memory")

__device__ __forceinline__ uint32_t smem_u32(const void* p) {
    return (uint32_t)__cvta_generic_to_shared(p);
}
__device__ __forceinline__ uint32_t h2u(__half2 h) { return *(uint32_t*)&h; }

// ---- global scratch (fp16) ----
// q: hi+lo fp16 [b*1024+t][64] (unscaled). k: single fp16 scaled by 768^-0.5.
// v: single fp16 transposed [b*64+d][1024]. All 16B-chunk XOR-swizzled by row&7.
__device__ __align__(16) __half g_qh[NB * NT * ND];
__device__ __align__(16) __half g_ql[NB * NT * ND];
__device__ __align__(16) __half g_kh[NB * NT * ND];
__device__ __align__(16) __half g_vth[NB * ND * NT];
__device__ __align__(16) __half g_Bh[192 * NC];
__device__ __align__(16) float2 g_rope[NT * 32];

// ---------------------------------------------------------------------------
// W conversion (fp16 single) + RoPE table fill
// ---------------------------------------------------------------------------
__global__ __launch_bounds__(256) void wconv_kernel(
    const float* __restrict__ Wq, const float* __restrict__ Wk, const float* __restrict__ Wv)
{
    int idx = blockIdx.x * 256 + threadIdx.x;
    if (idx < NT * 32) {
        int t = idx >> 5, pi = idx & 31;
        float freq = expf((float)(2 * pi) * (-9.210340371976184f / (float)ND));
        float sv, cv;
        sincosf((float)t * freq, &sv, &cv);
        g_rope[idx] = make_float2(cv, sv);
    }
    int mat = idx / 49152;
    int r = idx - mat * 49152;
    int n = r / NC;
    int k = r - n * NC;
    const float* W = (mat == 0) ? Wq : (mat == 1) ? Wk : Wv;
    g_Bh[idx] = __float2half_rn(W[k * ND + n]);
}

// ---------------------------------------------------------------------------
// Fused QKV GEMM (fp16 2-term), r16 mainloop. M=64/CTA, N=192, K-chunk 64.
// Epilogue: q -> fp16 hi/lo (unscaled); k -> single fp16 * 768^-0.5; v -> fp16.
// ---------------------------------------------------------------------------
#define QK_AH 0
#define QK_AL 18432
#define QK_B  36864
#define QK_ABUF 9216
#define QK_BSZ 27648
#define QKV_SMEM 92160

__global__ __launch_bounds__(256, 2) void qkv_mma(const float* __restrict__ x)
{
    extern __shared__ __align__(16) char sm[];
    const uint32_t smb = smem_u32(sm);

    const int tid = threadIdx.x;
    const int lane = tid & 31, w = tid >> 5;
    const int warpM = w & 1, warpN = w >> 1;
    const int g = lane >> 2, qd = lane & 3;
    const int m0 = blockIdx.x * 64;

    float acc[2][6][4];
#pragma unroll
    for (int mt = 0; mt < 2; mt++)
#pragma unroll
        for (int nt = 0; nt < 6; nt++)
#pragma unroll
            for (int i = 0; i < 4; i++) acc[mt][nt][i] = 0.f;

    const int am = tid >> 2, kq = tid & 3;
    const float* xrow = x + (size_t)(m0 + am) * NC + kq * 16;
    const uint32_t asoff = am * 144 + kq * 32;

    const uint32_t aoff = (uint32_t)((warpM * 32 + (lane & 15)) * 144 + ((lane >> 4) << 4));
    const uint32_t boff = (uint32_t)((warpN * 48 + (lane & 7) + ((lane >> 4) << 3)) * 144
                                     + (((lane >> 3) & 1) << 4));

    float4 rA[4];
#pragma unroll
    for (int j = 0; j < 4; j++) rA[j] = *(const float4*)(xrow + j * 4);
#pragma unroll
    for (int i = 0; i < 6; i++) {
        int id = i * 256 + tid;
        int row = id >> 3, q = id & 7;
        CP16(smb + QK_B + row * 144 + q * 16, (const char*)(g_Bh + row * NC) + q * 16);
    }
    CP_COMMIT();

#pragma unroll 2
    for (int c = 0; c < 12; c++) {
        const int sa = c & 1;
        const uint32_t ahb = smb + QK_AH + sa * QK_ABUF;
        const uint32_t bbb = smb + QK_B + sa * QK_BSZ;

        {
            uint32_t h[8], l[8];
#pragma unroll
            for (int j = 0; j < 4; j++) {
                float4 f = rA[j];
                __half2 hh0 = __floats2half2_rn(f.x, f.y);
                __half2 hh1 = __floats2half2_rn(f.z, f.w);
                __half2 ll0 = __floats2half2_rn(f.x - __low2float(hh0), f.y - __high2float(hh0));
                __half2 ll1 = __floats2half2_rn(f.z - __low2float(hh1), f.w - __high2float(hh1));
                h[2 * j] = h2u(hh0); h[2 * j + 1] = h2u(hh1);
                l[2 * j] = h2u(ll0); l[2 * j + 1] = h2u(ll1);
            }
            char* base = sm + sa * QK_ABUF;
            *(uint4*)(base + QK_AH + asoff)      = make_uint4(h[0], h[1], h[2], h[3]);
            *(uint4*)(base + QK_AH + asoff + 16) = make_uint4(h[4], h[5], h[6], h[7]);
            *(uint4*)(base + QK_AL + asoff)      = make_uint4(l[0], l[1], l[2], l[3]);
            *(uint4*)(base + QK_AL + asoff + 16) = make_uint4(l[4], l[5], l[6], l[7]);
        }
        if (c + 1 < 12) {
#pragma unroll
            for (int j = 0; j < 4; j++)
                rA[j] = *(const float4*)(xrow + (c + 1) * 64 + j * 4);
        }

        CP_WAIT0();
        __syncthreads();

        if (c + 1 < 12) {
            const uint32_t nst = smb + QK_B + (sa ^ 1) * QK_BSZ;
#pragma unroll
            for (int i = 0; i < 6; i++) {
                int id = i * 256 + tid;
                int row = id >> 3, q = id & 7;
                CP16(nst + row * 144 + q * 16,
                     (const char*)(g_Bh + row * NC + (c + 1) * 64) + q * 16);
            }
            CP_COMMIT();
        }

#pragma unroll
        for (int ks = 0; ks < 4; ks++) {
            uint32_t ah[2][4], al[2][4];
#pragma unroll
            for (int mt = 0; mt < 2; mt++) {
                uint32_t a = ahb + aoff + mt * (16 * 144) + ks * 32;
                LDM4(ah[mt], a);
                LDM4(al[mt], a + (QK_AL - QK_AH));
            }
#pragma unroll
            for (int p = 0; p < 3; p++) {
                uint32_t bh4[4];
                uint32_t ba = bbb + boff + p * (16 * 144) + ks * 32;
                LDM4(bh4, ba);
                mma_f16(acc[0][2 * p],     ah[0], bh4);
                mma_f16(acc[0][2 * p + 1], ah[0], bh4 + 2);
                mma_f16(acc[1][2 * p],     ah[1], bh4);
                mma_f16(acc[1][2 * p + 1], ah[1], bh4 + 2);
                mma_f16(acc[0][2 * p],     al[0], bh4);
                mma_f16(acc[0][2 * p + 1], al[0], bh4 + 2);
                mma_f16(acc[1][2 * p],     al[1], bh4);
                mma_f16(acc[1][2 * p + 1], al[1], bh4 + 2);
            }
        }
    }
    __syncthreads();

    // ---- epilogue: q fp16 h+l (unscaled), k fp16 scaled, v fp16 ----
    float* vsm = (float*)sm;   // [64 d][68 m]
#pragma unroll
    for (int nt = 0; nt < 6; nt++) {
        int col0 = warpN * 48 + nt * 8 + qd * 2;
        if (col0 < 128) {
            int mat = col0 >> 6;
            int cin = col0 & 63;
            float sc = (mat == 0) ? 1.0f : 0.03608439182435161f;  // scale folded into k
            int pi = cin >> 1;
            int chunk = cin >> 3;
            int bw = (cin & 7) * 2;
#pragma unroll
            for (int mt = 0; mt < 2; mt++) {
#pragma unroll
                for (int half = 0; half < 2; half++) {
                    int ml = warpM * 32 + mt * 16 + g + half * 8;
                    int r = m0 + ml;
                    float2 cs = g_rope[((r & (NT - 1)) << 5) + pi];
                    float e = acc[mt][nt][half * 2], o = acc[mt][nt][half * 2 + 1];
                    float re = (e * cs.x - o * cs.y) * sc;
                    float ro = (e * cs.y + o * cs.x) * sc;
                    size_t byte = (size_t)r * 128 + 16 * (chunk ^ (ml & 7)) + bw;
                    __half2 hh = __floats2half2_rn(re, ro);
                    if (mat == 0) {
                        __half2 ll = __floats2half2_rn(re - __low2float(hh),
                                                       ro - __high2float(hh));
                        *(uint32_t*)((char*)g_qh + byte) = h2u(hh);
                        *(uint32_t*)((char*)g_ql + byte) = h2u(ll);
                    } else {
                        *(uint32_t*)((char*)g_kh + byte) = h2u(hh);
                    }
                }
            }
        } else {
            int cin = col0 & 63;
#pragma unroll
            for (int mt = 0; mt < 2; mt++) {
#pragma unroll
                for (int half = 0; half < 2; half++) {
                    int ml = warpM * 32 + mt * 16 + g + half * 8;
                    vsm[cin * 68 + ml]       = acc[mt][nt][half * 2];
                    vsm[(cin + 1) * 68 + ml] = acc[mt][nt][half * 2 + 1];
                }
            }
        }
    }
    __syncthreads();
    {
        const int bb = m0 >> 10;
        const int t0l = m0 & (NT - 1);
#pragma unroll
        for (int i = 0; i < 8; i++) {
            int idx = tid + i * 256;
            int d = idx >> 5;
            int pr = idx & 31;
            int tl = pr * 2;
            __half2 hh = __floats2half2_rn(vsm[d * 68 + tl], vsm[d * 68 + tl + 1]);
            size_t byte = ((size_t)(bb * 64 + d) * 1024 + t0l) * 2
                        + 16 * ((tl >> 3) ^ (d & 7)) + (tl & 7) * 2;
            *(uint32_t*)((char*)g_vth + byte) = h2u(hh);
        }
    }
}

// ---------------------------------------------------------------------------
// Flash attention, fp16 2-term everywhere: S = (qh+ql) x k, PV = (ph+pl) x v.
// BM=128 (8 warps x 16 rows), BN=64. 2-stage cp.async (16KB/stage).
// smem 65536 B: QH 0, QL 16384; stages at 32768: K +0 (8KB), V +8192 (8KB).
// ---------------------------------------------------------------------------
#define AQ_H 0
#define AQ_L 16384
#define A_ST 32768
#define A_STAGE 16384
#define ATTN_SMEM 65536

__global__ __launch_bounds__(256, 2) void attn_mma(float* __restrict__ out)
{
    extern __shared__ __align__(16) char sm[];
    const uint32_t smb = smem_u32(sm);

    const int tid = threadIdx.x;
    const int lane = tid & 31, w = tid >> 5;
    const int g = lane >> 2, qd = lane & 3;
    const int bid = (int)blockIdx.x;
    const int rk = (bid < 148) ? bid : 403 - bid;
    const int qt = 7 - (rk >> 5);
    const int b = rk & 31;
    const int q0 = qt * 128;
    const int jmax = 2 * qt + 1;

    // prologue: Q (hi+lo) + KV(0)
    {
        const char* qH = (const char*)(g_qh + (size_t)(b * NT + q0) * ND);
        const char* qL = (const char*)(g_ql + (size_t)(b * NT + q0) * ND);
#pragma unroll
        for (int i = 0; i < 4; i++) {
            int idx = tid + i * 256;
            CP16(smb + AQ_H + idx * 16, qH + idx * 16);
            CP16(smb + AQ_L + idx * 16, qL + idx * 16);
        }
        const char* kH = (const char*)(g_kh + (size_t)(b * NT) * ND);
#pragma unroll
        for (int i = 0; i < 2; i++) {
            int idx = tid + i * 256;
            CP16(smb + A_ST + idx * 16, kH + idx * 16);
            int d = idx >> 3, c = idx & 7;
            size_t vb = (size_t)(b * 64 + d) * 2048 + c * 16;
            CP16(smb + A_ST + 8192 + idx * 16, (const char*)g_vth + vb);
        }
        CP_COMMIT();
    }

    float o[8][4];
    float m_r[2], l_r[2];
#pragma unroll
    for (int nd = 0; nd < 8; nd++)
#pragma unroll
        for (int i = 0; i < 4; i++) o[nd][i] = 0.f;
    m_r[0] = m_r[1] = -INFINITY;
    l_r[0] = l_r[1] = 0.f;

    const uint32_t aoffQ = (uint32_t)((w * 16 + (lane & 15)) * 128);
    const uint32_t browB = (uint32_t)((lane & 7) + ((lane >> 4) << 3));
    const int lx = lane & 7, lb = (lane >> 3) & 1;
    const int rmax = q0 + w * 16 + 15;

    CP_WAIT0();
    __syncthreads();

    for (int jt = 0; jt <= jmax; jt++) {
        const int s = jt & 1;
        const uint32_t stb = smb + A_ST + s * A_STAGE;

        if (jt > 0) { CP_WAIT0(); __syncthreads(); }

        if (jt < jmax) {
            const int kvn = (jt + 1) * 64;
            const uint32_t nst = smb + A_ST + (s ^ 1) * A_STAGE;
            const char* kH = (const char*)(g_kh + (size_t)(b * NT + kvn) * ND);
#pragma unroll
            for (int i = 0; i < 2; i++) {
                int idx = tid + i * 256;
                CP16(nst + idx * 16, kH + idx * 16);
                int d = idx >> 3, c = idx & 7;
                size_t vb = ((size_t)(b * 64 + d) * 1024 + kvn) * 2 + c * 16;
                CP16(nst + 8192 + idx * 16, (const char*)g_vth + vb);
            }
            CP_COMMIT();
        }

        if (jt * 64 > rmax) continue;
        const bool diag = (jt >= 2 * qt);

        // ---- S = (Qh + Ql) @ K^T ----
        float s_[8][4];
#pragma unroll
        for (int nt = 0; nt < 8; nt++)
#pragma unroll
            for (int i = 0; i < 4; i++) s_[nt][i] = 0.f;

#pragma unroll
        for (int ks = 0; ks < 4; ks++) {
            uint32_t qh4[4], ql4[4];
            uint32_t chQ = (uint32_t)(((2 * ks + (lane >> 4)) ^ lx) * 16);
            LDM4(qh4, smb + AQ_H + aoffQ + chQ);
            LDM4(ql4, smb + AQ_L + aoffQ + chQ);
            uint32_t ch = (uint32_t)(((2 * ks + lb) ^ lx) * 16);
#pragma unroll
            for (int ntp = 0; ntp < 4; ntp++) {
                if (diag && jt * 64 + ntp * 16 > rmax) continue;
                uint32_t kb4[4];
                uint32_t ba = stb + (ntp * 16 + browB) * 128 + ch;
                LDM4(kb4, ba);
                mma_f16(s_[2 * ntp], qh4, kb4);
                mma_f16(s_[2 * ntp], ql4, kb4);
                mma_f16(s_[2 * ntp + 1], qh4, kb4 + 2);
                mma_f16(s_[2 * ntp + 1], ql4, kb4 + 2);
            }
        }

        if (diag) {
#pragma unroll
            for (int nt = 0; nt < 8; nt++) {
                int col = jt * 64 + nt * 8 + qd * 2;
#pragma unroll
                for (int half = 0; half < 2; half++) {
                    int row = q0 + w * 16 + g + half * 8;
                    if (col > row)     s_[nt][half * 2]     = -INFINITY;
                    if (col + 1 > row) s_[nt][half * 2 + 1] = -INFINITY;
                }
            }
        }

        // ---- online softmax ----
#pragma unroll
        for (int half = 0; half < 2; half++) {
            float mx = -INFINITY;
#pragma unroll
            for (int nt = 0; nt < 8; nt++)
                mx = fmaxf(mx, fmaxf(s_[nt][half * 2], s_[nt][half * 2 + 1]));
            mx = fmaxf(mx, __shfl_xor_sync(0xffffffffu, mx, 1));
            mx = fmaxf(mx, __shfl_xor_sync(0xffffffffu, mx, 2));
            float mn = fmaxf(m_r[half], mx);
            float alpha = __expf(m_r[half] - mn);
            m_r[half] = mn;
            float sum = 0.f;
#pragma unroll
            for (int nt = 0; nt < 8; nt++) {
                float p0 = __expf(s_[nt][half * 2] - mn);
                float p1 = __expf(s_[nt][half * 2 + 1] - mn);
                s_[nt][half * 2] = p0;
                s_[nt][half * 2 + 1] = p1;
                sum += p0 + p1;
            }
            sum += __shfl_xor_sync(0xffffffffu, sum, 1);
            sum += __shfl_xor_sync(0xffffffffu, sum, 2);
            l_r[half] = l_r[half] * alpha + sum;
#pragma unroll
            for (int nd = 0; nd < 8; nd++) {
                o[nd][half * 2] *= alpha;
                o[nd][half * 2 + 1] *= alpha;
            }
        }

        // ---- O += (Ph + Pl) @ V ----
#pragma unroll
        for (int ks = 0; ks < 4; ks++) {
            if (diag && jt * 64 + ks * 16 > rmax) continue;
            uint32_t ph[4], pl[4];
#pragma unroll
            for (int u = 0; u < 2; u++) {
                int nt = 2 * ks + u;
                __half2 h0 = __floats2half2_rn(s_[nt][0], s_[nt][1]);
                __half2 h1 = __floats2half2_rn(s_[nt][2], s_[nt][3]);
                __half2 l0 = __floats2half2_rn(s_[nt][0] - __low2float(h0),
                                               s_[nt][1] - __high2float(h0));
                __half2 l1 = __floats2half2_rn(s_[nt][2] - __low2float(h1),
                                               s_[nt][3] - __high2float(h1));
                ph[2 * u] = h2u(h0); ph[2 * u + 1] = h2u(h1);
                pl[2 * u] = h2u(l0); pl[2 * u + 1] = h2u(l1);
            }
            uint32_t ch = (uint32_t)(((2 * ks + lb) ^ lx) * 16);
#pragma unroll
            for (int ntp = 0; ntp < 4; ntp++) {
                uint32_t vb4[4];
                uint32_t ba = stb + 8192 + (ntp * 16 + browB) * 128 + ch;
                LDM4(vb4, ba);
                mma_f16(o[2 * ntp], ph, vb4);
                mma_f16(o[2 * ntp], pl, vb4);
                mma_f16(o[2 * ntp + 1], ph, vb4 + 2);
                mma_f16(o[2 * ntp + 1], pl, vb4 + 2);
            }
        }
    }

    // epilogue
    float inv0 = 1.f / l_r[0];
    float inv1 = 1.f / l_r[1];
    int row0 = b * NT + q0 + w * 16 + g;
#pragma unroll
    for (int nd = 0; nd < 8; nd++) {
        int d = nd * 8 + qd * 2;
        *(float2*)(out + (size_t)row0 * ND + d) =
            make_float2(o[nd][0] * inv0, o[nd][1] * inv0);
        *(float2*)(out + (size_t)(row0 + 8) * ND + d) =
            make_float2(o[nd][2] * inv1, o[nd][3] * inv1);
    }
}

extern "C" void kernel_launch(void* const* d_in, const int* in_sizes, int n_in,
                              void* d_out, int out_size) {
    (void)in_sizes; (void)n_in; (void)out_size;
    const float* x  = (const float*)d_in[0];
    const float* Wq = (const float*)d_in[1];
    const float* Wk = (const float*)d_in[2];
    const float* Wv = (const float*)d_in[3];
    float* out = (float*)d_out;

    cudaFuncSetAttribute(qkv_mma, cudaFuncAttributeMaxDynamicSharedMemorySize, QKV_SMEM);
    cudaFuncSetAttribute(attn_mma, cudaFuncAttributeMaxDynamicSharedMemorySize, ATTN_SMEM);

    wconv_kernel<<<576, 256>>>(Wq, Wk, Wv);
    qkv_mma<<<512, 256, QKV_SMEM>>>(x);
    attn_mma<<<256, 256, ATTN_SMEM>>>(out);
}